// round 1
// baseline (speedup 1.0000x reference)
#include <cuda_runtime.h>
#include <math.h>

#define N_USERS 10000
#define N_ITEMS 30000
#define N_NODES 40000
#define HID     256
#define N_EDGES 500000
#define AH      32

// ---------------- scratch (static device allocations only) ----------------
__device__ float g_U1[N_USERS * AH];        // user_emb @ W1[:256]
__device__ float g_I1[N_ITEMS * AH];        // item_emb @ W1[256:] + b1
__device__ float g_ew[N_EDGES];             // raw sigmoid edge weights
__device__ int   g_ksrc[N_EDGES];           // compacted kept edges
__device__ int   g_kdst[N_EDGES];
__device__ float g_deg[N_USERS];            // in-degree (+1 self loop); dst < N_USERS by construction
__device__ float g_dinv[N_USERS];
__device__ float g_xw[(size_t)N_NODES * HID];
__device__ int   g_cnt[2];                  // [0]=pass count, [1]=compact counter
__device__ unsigned long long g_maxpack;    // (w_bits<<32) | ~e  -> argmax with first-index tiebreak

// ---------------- K0: per-launch state reset (graph replay safe) ----------
__global__ void k_reset() {
    int i = blockIdx.x * blockDim.x + threadIdx.x;
    if (i < N_USERS) g_deg[i] = 1.0f;
    if (i == 0) { g_cnt[0] = 0; g_cnt[1] = 0; g_maxpack = 0ull; }
}

// ---------------- K1: attention MLP layer-1 precompute --------------------
// One warp per node row. W1 half (256x32 = 32KB) staged in smem.
// Blocks 0..1249 -> users (rows 0..9999), blocks 1250..4999 -> items.
__global__ __launch_bounds__(256) void k_attn_pre(
    const float* __restrict__ ue, const float* __restrict__ ie,
    const float* __restrict__ W1, const float* __restrict__ b1) {
    __shared__ float Ws[256 * 32];
    const int lane = threadIdx.x & 31;
    const int wrp  = threadIdx.x >> 5;
    const int rowBase = blockIdx.x * 8;
    const bool isUser = rowBase < N_USERS;          // N_USERS % 8 == 0 -> no mixed block
    const float* Wsrc = W1 + (isUser ? 0 : 256 * 32);
    for (int i = threadIdx.x; i < 256 * 32; i += blockDim.x) Ws[i] = Wsrc[i];
    __syncthreads();

    const int row = rowBase + wrp;                  // always < N_NODES (5000*8 == 40000)
    const float* x = isUser ? (ue + (size_t)row * HID)
                            : (ie + (size_t)(row - N_USERS) * HID);
    float acc = isUser ? 0.0f : b1[lane];           // fold b1 into item half
    #pragma unroll
    for (int kb = 0; kb < 8; kb++) {
        float xv = x[kb * 32 + lane];               // coalesced
        #pragma unroll
        for (int j = 0; j < 32; j++) {
            float a = __shfl_sync(0xffffffffu, xv, j);
            acc = fmaf(a, Ws[(kb * 32 + j) * 32 + lane], acc);
        }
    }
    if (isUser) g_U1[row * AH + lane] = acc;
    else        g_I1[(row - N_USERS) * AH + lane] = acc;
}

// ---------------- K2: per-edge MLP tail + sigmoid + stats -----------------
__global__ __launch_bounds__(256) void k_edge(
    const int* __restrict__ ei, const float* __restrict__ W2,
    const float* __restrict__ b2) {
    __shared__ float w2s[32];
    __shared__ float b2s;
    if (threadIdx.x < 32) w2s[threadIdx.x] = W2[threadIdx.x];
    if (threadIdx.x == 0) b2s = b2[0];
    __syncthreads();

    const int e = blockIdx.x * blockDim.x + threadIdx.x;
    bool pass = false;
    unsigned long long pack = 0ull;
    if (e < N_EDGES) {
        const int s = ei[e];
        const int d = ei[N_EDGES + e];
        const float4* up = (const float4*)(g_U1 + (size_t)s * AH);
        const float4* ip = (const float4*)(g_I1 + (size_t)d * AH);
        float logit = b2s;
        #pragma unroll
        for (int q = 0; q < 8; q++) {
            float4 u = up[q], v = ip[q];
            float h;
            h = u.x + v.x; h = h > 0.0f ? h : 0.2f * h; logit = fmaf(h, w2s[q * 4 + 0], logit);
            h = u.y + v.y; h = h > 0.0f ? h : 0.2f * h; logit = fmaf(h, w2s[q * 4 + 1], logit);
            h = u.z + v.z; h = h > 0.0f ? h : 0.2f * h; logit = fmaf(h, w2s[q * 4 + 2], logit);
            h = u.w + v.w; h = h > 0.0f ? h : 0.2f * h; logit = fmaf(h, w2s[q * 4 + 3], logit);
        }
        float w = 1.0f / (1.0f + expf(-logit));
        g_ew[e] = w;
        pass = (w > 0.8f);
        pack = ((unsigned long long)__float_as_uint(w) << 32)
             | (unsigned long long)(~(unsigned)e);
    }
    unsigned m = __ballot_sync(0xffffffffu, pass);
    #pragma unroll
    for (int off = 16; off; off >>= 1) {
        unsigned long long o = __shfl_down_sync(0xffffffffu, pack, off);
        if (o > pack) pack = o;
    }
    if ((threadIdx.x & 31) == 0) {
        if (m) atomicAdd(&g_cnt[0], __popc(m));
        atomicMax(&g_maxpack, pack);
    }
}

// ---------------- K3: denoise mask + compact kept edges + degree ----------
__global__ __launch_bounds__(256) void k_denoise(
    const int* __restrict__ ei, float* __restrict__ out_w) {
    const int e = blockIdx.x * blockDim.x + threadIdx.x;
    if (e >= N_EDGES) return;
    const float w = g_ew[e];
    bool keep;
    if (g_cnt[0] > 0) {
        keep = (w > 0.8f);
    } else {
        // fallback: only the first argmax edge survives
        keep = (e == (int)(~(unsigned)(g_maxpack & 0xffffffffull)));
    }
    out_w[e] = keep ? w : 0.0f;
    if (keep) {
        const int s = ei[e];
        const int d = ei[N_EDGES + e];
        int pos = atomicAdd(&g_cnt[1], 1);
        g_ksrc[pos] = s;
        g_kdst[pos] = d;
        atomicAdd(&g_deg[d], 1.0f);
    }
}

// ---------------- K4: dinv = rsqrt(deg) -----------------------------------
__global__ void k_dinv() {
    int i = blockIdx.x * blockDim.x + threadIdx.x;
    if (i < N_USERS) g_dinv[i] = rsqrtf(g_deg[i]);
}

// ---------------- K5: GCN GEMM xw = x @ W, fused self-loop + bias ---------
#define BM 64
#define BN 64
#define BK 16
__global__ __launch_bounds__(256) void k_gcn_gemm(
    const float* __restrict__ ue, const float* __restrict__ ie,
    const float* __restrict__ W, const float* __restrict__ b,
    float* __restrict__ out) {
    __shared__ float As[BM][BK];
    __shared__ float Bs[BK][BN];
    const int t  = threadIdx.x;
    const int tx = t & 15;
    const int ty = t >> 4;
    const int row0 = blockIdx.y * BM;
    const int c0   = blockIdx.x * BN;

    const int arow = t >> 2;              // 0..63
    const int akq  = (t & 3) * 4;         // 0,4,8,12
    const int brow = t >> 4;              // 0..15
    const int bc   = (t & 15) * 4;        // 0..60

    const int grow = row0 + arow;
    const float* xrow = (grow < N_USERS) ? (ue + (size_t)grow * HID)
                                         : (ie + (size_t)(grow - N_USERS) * HID);
    float acc[4][4] = {};

    for (int k0 = 0; k0 < HID; k0 += BK) {
        float4 av = *(const float4*)(xrow + k0 + akq);
        float4 bv = *(const float4*)(W + (size_t)(k0 + brow) * HID + c0 + bc);
        __syncthreads();
        *(float4*)&As[arow][akq] = av;
        *(float4*)&Bs[brow][bc]  = bv;
        __syncthreads();
        #pragma unroll
        for (int kk = 0; kk < BK; kk++) {
            float a[4];
            #pragma unroll
            for (int i = 0; i < 4; i++) a[i] = As[ty * 4 + i][kk];
            float4 bf = *(const float4*)&Bs[kk][tx * 4];
            #pragma unroll
            for (int i = 0; i < 4; i++) {
                acc[i][0] = fmaf(a[i], bf.x, acc[i][0]);
                acc[i][1] = fmaf(a[i], bf.y, acc[i][1]);
                acc[i][2] = fmaf(a[i], bf.z, acc[i][2]);
                acc[i][3] = fmaf(a[i], bf.w, acc[i][3]);
            }
        }
    }

    #pragma unroll
    for (int i = 0; i < 4; i++) {
        const int n = row0 + ty * 4 + i;
        float dv = (n < N_USERS) ? g_dinv[n] : 1.0f;
        float dsq = dv * dv;
        #pragma unroll
        for (int j = 0; j < 4; j++) {
            const int c = c0 + tx * 4 + j;
            float v = acc[i][j];
            g_xw[(size_t)n * HID + c] = v;
            out[(size_t)n * HID + c]  = fmaf(v, dsq, b[c]);
        }
    }
}

// ---------------- K6: scatter messages (vectorized L2 reductions) ---------
__global__ __launch_bounds__(256) void k_scatter(float* __restrict__ out) {
    const int kept = g_cnt[1];
    const long long total = (long long)kept * (HID / 4);   // float4 chunks
    const long long stride = (long long)gridDim.x * blockDim.x;
    for (long long idx = (long long)blockIdx.x * blockDim.x + threadIdx.x;
         idx < total; idx += stride) {
        const int i = (int)(idx >> 6);          // edge index (HID/4 == 64)
        const int q = (int)(idx & 63);          // chunk within row
        const int s = g_ksrc[i];
        const int d = g_kdst[i];
        const float coef = g_dinv[s] * g_dinv[d];
        float4 v = *(const float4*)(g_xw + (size_t)s * HID + q * 4);
        float* p = out + (size_t)d * HID + q * 4;
        asm volatile("red.global.add.v4.f32 [%0], {%1,%2,%3,%4};"
                     :: "l"(p), "f"(v.x * coef), "f"(v.y * coef),
                        "f"(v.z * coef), "f"(v.w * coef)
                     : "memory");
    }
}

// ---------------- host launch ---------------------------------------------
extern "C" void kernel_launch(void* const* d_in, const int* in_sizes, int n_in,
                              void* d_out, int out_size) {
    const float* ue = (const float*)d_in[0];   // user_embeddings [10000,256]
    const float* ie = (const float*)d_in[1];   // item_embeddings [30000,256]
    const int*   ei = (const int*)  d_in[2];   // edge_index [2,500000]
    const float* W1 = (const float*)d_in[3];   // [512,32]
    const float* b1 = (const float*)d_in[4];   // [32]
    const float* W2 = (const float*)d_in[5];   // [32,1]
    const float* b2 = (const float*)d_in[6];   // [1]
    const float* gW = (const float*)d_in[7];   // [256,256]
    const float* gb = (const float*)d_in[8];   // [256]
    float* out   = (float*)d_out;                       // gcn output [40000,256]
    float* out_w = out + (size_t)N_NODES * HID;         // denoised weights [500000]

    k_reset<<<(N_USERS + 255) / 256, 256>>>();
    k_attn_pre<<<N_NODES / 8, 256>>>(ue, ie, W1, b1);
    k_edge<<<(N_EDGES + 255) / 256, 256>>>(ei, W2, b2);
    k_denoise<<<(N_EDGES + 255) / 256, 256>>>(ei, out_w);
    k_dinv<<<(N_USERS + 255) / 256, 256>>>();
    dim3 gemm_grid(HID / BN, N_NODES / BM);
    k_gcn_gemm<<<gemm_grid, 256>>>(ue, ie, gW, gb, out);
    k_scatter<<<1024, 256>>>(out);
}

// round 5
// speedup vs baseline: 1.3220x; 1.3220x over previous
#include <cuda_runtime.h>
#include <cuda_bf16.h>
#include <math.h>
#include <stdint.h>

#define N_USERS 10000
#define N_ITEMS 30000
#define N_NODES 40000
#define HID     256
#define N_EDGES 500000
#define AH      32

// ---------------- scratch (static device allocations only) ----------------
__device__ float g_U1[N_USERS * AH];
__device__ float g_I1[N_ITEMS * AH];
__device__ float g_ew[N_EDGES];
__device__ int   g_ksrc[N_EDGES];
__device__ int   g_kdst[N_EDGES];
__device__ float g_deg[N_USERS];
__device__ float g_dinv[N_USERS];
__device__ float g_xw[(size_t)N_NODES * HID];
__device__ int   g_cnt[2];
__device__ unsigned long long g_maxpack;
// bf16-split operands for the tensor-core GEMM (K-major)
__device__ __align__(16) __nv_bfloat16 g_Xhi[(size_t)N_NODES * HID];
__device__ __align__(16) __nv_bfloat16 g_Xlo[(size_t)N_NODES * HID];
__device__ __align__(16) __nv_bfloat16 g_Whi[HID * HID];   // W^T: [n][k]
__device__ __align__(16) __nv_bfloat16 g_Wlo[HID * HID];

// ---------------- helpers ---------------------------------------------------
__device__ __forceinline__ uint32_t smem_u32(const void* p) {
    uint32_t a;
    asm("{ .reg .u64 t; cvta.to.shared.u64 t, %1; cvt.u32.u64 %0, t; }" : "=r"(a) : "l"(p));
    return a;
}
__device__ __forceinline__ void ldsm4(uint32_t* f, uint32_t addr) {
    asm volatile("ldmatrix.sync.aligned.m8n8.x4.shared.b16 {%0,%1,%2,%3}, [%4];"
        : "=r"(f[0]), "=r"(f[1]), "=r"(f[2]), "=r"(f[3]) : "r"(addr));
}
__device__ __forceinline__ void mma16816(float* d, const uint32_t* a, uint32_t b0, uint32_t b1) {
    asm volatile("mma.sync.aligned.m16n8k16.row.col.f32.bf16.bf16.f32 "
        "{%0,%1,%2,%3}, {%4,%5,%6,%7}, {%8,%9}, {%0,%1,%2,%3};"
        : "+f"(d[0]), "+f"(d[1]), "+f"(d[2]), "+f"(d[3])
        : "r"(a[0]), "r"(a[1]), "r"(a[2]), "r"(a[3]), "r"(b0), "r"(b1));
}
#define CP_ASYNC16(s, g) asm volatile("cp.async.cg.shared.global [%0], [%1], 16;" :: "r"(s), "l"(g))
#define CP_COMMIT()      asm volatile("cp.async.commit_group;" ::: "memory")
#define CP_WAIT(n)       asm volatile("cp.async.wait_group %0;" :: "n"(n) : "memory")

// swizzled smem offset for tile element chunk: row r (128B rows), 16B chunk kb
__device__ __forceinline__ uint32_t swaddr(uint32_t base, int r, int kb) {
    return base + (uint32_t)(r * 128) + (uint32_t)(((kb ^ (r & 7)) << 4));
}

// ---------------- K0: per-launch state reset ------------------------------
__global__ void k_reset() {
    int i = blockIdx.x * blockDim.x + threadIdx.x;
    if (i < N_USERS) g_deg[i] = 1.0f;
    if (i == 0) { g_cnt[0] = 0; g_cnt[1] = 0; g_maxpack = 0ull; }
}

// ---------------- K_conv: fp32 -> bf16 hi/lo splits -----------------------
__global__ __launch_bounds__(256) void k_conv_x(const float* __restrict__ ue,
                                                const float* __restrict__ ie) {
    int i = blockIdx.x * blockDim.x + threadIdx.x;   // one float4 per thread
    if (i >= N_NODES * (HID / 4)) return;
    int row = i >> 6, q = i & 63;
    const float* src = (row < N_USERS) ? (ue + (size_t)row * HID)
                                       : (ie + (size_t)(row - N_USERS) * HID);
    float4 v = ((const float4*)src)[q];
    __nv_bfloat162 h0 = __float22bfloat162_rn(make_float2(v.x, v.y));
    __nv_bfloat162 h1 = __float22bfloat162_rn(make_float2(v.z, v.w));
    float2 f0 = __bfloat1622float2(h0), f1 = __bfloat1622float2(h1);
    __nv_bfloat162 l0 = __float22bfloat162_rn(make_float2(v.x - f0.x, v.y - f0.y));
    __nv_bfloat162 l1 = __float22bfloat162_rn(make_float2(v.z - f1.x, v.w - f1.y));
    ((__nv_bfloat162*)g_Xhi)[i * 2]     = h0;
    ((__nv_bfloat162*)g_Xhi)[i * 2 + 1] = h1;
    ((__nv_bfloat162*)g_Xlo)[i * 2]     = l0;
    ((__nv_bfloat162*)g_Xlo)[i * 2 + 1] = l1;
}

__global__ __launch_bounds__(256) void k_conv_w(const float* __restrict__ W) {
    int i = blockIdx.x * blockDim.x + threadIdx.x;   // i = n*256 + k
    if (i >= HID * HID) return;
    int n = i >> 8, k = i & 255;
    float v = W[k * HID + n];
    __nv_bfloat16 h = __float2bfloat16(v);
    g_Whi[i] = h;
    g_Wlo[i] = __float2bfloat16(v - __bfloat162float(h));
}

// ---------------- K1: attention MLP layer-1 precompute --------------------
__global__ __launch_bounds__(256) void k_attn_pre(
    const float* __restrict__ ue, const float* __restrict__ ie,
    const float* __restrict__ W1, const float* __restrict__ b1) {
    __shared__ float Ws[256 * 32];
    const int lane = threadIdx.x & 31;
    const int wrp  = threadIdx.x >> 5;
    const int rowBase = blockIdx.x * 8;
    const bool isUser = rowBase < N_USERS;
    const float* Wsrc = W1 + (isUser ? 0 : 256 * 32);
    for (int i = threadIdx.x; i < 256 * 32; i += blockDim.x) Ws[i] = Wsrc[i];
    __syncthreads();

    const int row = rowBase + wrp;
    const float* x = isUser ? (ue + (size_t)row * HID)
                            : (ie + (size_t)(row - N_USERS) * HID);
    float acc = isUser ? 0.0f : b1[lane];
    #pragma unroll
    for (int kb = 0; kb < 8; kb++) {
        float xv = x[kb * 32 + lane];
        #pragma unroll
        for (int j = 0; j < 32; j++) {
            float a = __shfl_sync(0xffffffffu, xv, j);
            acc = fmaf(a, Ws[(kb * 32 + j) * 32 + lane], acc);
        }
    }
    if (isUser) g_U1[row * AH + lane] = acc;
    else        g_I1[(row - N_USERS) * AH + lane] = acc;
}

// ---------------- K2: per-edge MLP tail + sigmoid + stats -----------------
__global__ __launch_bounds__(256) void k_edge(
    const int* __restrict__ ei, const float* __restrict__ W2,
    const float* __restrict__ b2) {
    __shared__ float w2s[32];
    __shared__ float b2s;
    if (threadIdx.x < 32) w2s[threadIdx.x] = W2[threadIdx.x];
    if (threadIdx.x == 0) b2s = b2[0];
    __syncthreads();

    const int e = blockIdx.x * blockDim.x + threadIdx.x;
    bool pass = false;
    unsigned long long pack = 0ull;
    if (e < N_EDGES) {
        const int s = ei[e];
        const int d = ei[N_EDGES + e];
        const float4* up = (const float4*)(g_U1 + (size_t)s * AH);
        const float4* ip = (const float4*)(g_I1 + (size_t)d * AH);
        float logit = b2s;
        #pragma unroll
        for (int q = 0; q < 8; q++) {
            float4 u = up[q], v = ip[q];
            float h;
            h = u.x + v.x; h = h > 0.0f ? h : 0.2f * h; logit = fmaf(h, w2s[q * 4 + 0], logit);
            h = u.y + v.y; h = h > 0.0f ? h : 0.2f * h; logit = fmaf(h, w2s[q * 4 + 1], logit);
            h = u.z + v.z; h = h > 0.0f ? h : 0.2f * h; logit = fmaf(h, w2s[q * 4 + 2], logit);
            h = u.w + v.w; h = h > 0.0f ? h : 0.2f * h; logit = fmaf(h, w2s[q * 4 + 3], logit);
        }
        float w = 1.0f / (1.0f + expf(-logit));
        g_ew[e] = w;
        pass = (w > 0.8f);
        pack = ((unsigned long long)__float_as_uint(w) << 32)
             | (unsigned long long)(~(unsigned)e);
    }
    unsigned m = __ballot_sync(0xffffffffu, pass);
    #pragma unroll
    for (int off = 16; off; off >>= 1) {
        unsigned long long o = __shfl_down_sync(0xffffffffu, pack, off);
        if (o > pack) pack = o;
    }
    if ((threadIdx.x & 31) == 0) {
        if (m) atomicAdd(&g_cnt[0], __popc(m));
        atomicMax(&g_maxpack, pack);
    }
}

// ---------------- K3: denoise + warp-aggregated compaction ----------------
__global__ __launch_bounds__(256) void k_denoise(
    const int* __restrict__ ei, float* __restrict__ out_w) {
    const int e = blockIdx.x * blockDim.x + threadIdx.x;
    bool keep = false;
    float w = 0.0f;
    if (e < N_EDGES) {
        w = g_ew[e];
        if (g_cnt[0] > 0) keep = (w > 0.8f);
        else keep = (e == (int)(~(unsigned)(g_maxpack & 0xffffffffull)));
        out_w[e] = keep ? w : 0.0f;
    }
    unsigned m = __ballot_sync(0xffffffffu, keep);
    if (!m) return;
    const int lane = threadIdx.x & 31;
    const int leader = __ffs(m) - 1;
    int base = 0;
    if (lane == leader) base = atomicAdd(&g_cnt[1], __popc(m));
    base = __shfl_sync(0xffffffffu, base, leader);
    if (keep) {
        const int rank = __popc(m & ((1u << lane) - 1));
        const int s = ei[e];
        const int d = ei[N_EDGES + e];
        g_ksrc[base + rank] = s;
        g_kdst[base + rank] = d;
        atomicAdd(&g_deg[d], 1.0f);
    }
}

// ---------------- K4: dinv = rsqrt(deg) -----------------------------------
__global__ void k_dinv() {
    int i = blockIdx.x * blockDim.x + threadIdx.x;
    if (i < N_USERS) g_dinv[i] = rsqrtf(g_deg[i]);
}

// ---------------- K5: HMMA bf16x3 GEMM, fused self-loop + bias ------------
// CTA: D[128x128] over K=256 in 4 chunks of 64. smem tiles per stage:
// {Ahi, Alo, Bhi, Blo}, each 128 rows x 128B (16KB), XOR-swizzled 16B chunks.
#define GT      16384
#define GSTAGE  (4 * GT)
#define GSMEM   (2 * GSTAGE)

__device__ __forceinline__ void stage_all(char* dst, int m0, int n0, int ko, int t) {
    uint32_t sb = smem_u32(dst);
    #pragma unroll
    for (int i = t; i < 1024; i += 256) {
        int r = i >> 3, kb = i & 7;
        int gr = m0 + r; if (gr > N_NODES - 1) gr = N_NODES - 1;
        size_t go = (size_t)gr * HID + ko + kb * 8;
        uint32_t so = sb + (uint32_t)(r * 128) + (uint32_t)(((kb ^ (r & 7)) << 4));
        CP_ASYNC16(so,          g_Xhi + go);
        CP_ASYNC16(so + GT,     g_Xlo + go);
        int br = n0 + r;                       // always < 256
        size_t bo = (size_t)br * HID + ko + kb * 8;
        CP_ASYNC16(so + 2 * GT, g_Whi + bo);
        CP_ASYNC16(so + 3 * GT, g_Wlo + bo);
    }
}

__global__ __launch_bounds__(256, 1) void k_gemm(const float* __restrict__ gb,
                                                 float* __restrict__ out) {
    extern __shared__ char smem[];
    const int t = threadIdx.x;
    const int l = t & 31, wrp = t >> 5;
    const int wm = wrp & 3, wn = wrp >> 2;     // warp tile: 32(M) x 64(N)
    const int m0 = blockIdx.x * 128, n0 = blockIdx.y * 128;
    const uint32_t sbase = smem_u32(smem);

    stage_all(smem, m0, n0, 0, t);
    CP_COMMIT();

    float acc[2][8][4] = {};
    const int rA = wm * 32 + (l & 15);
    const int rB = wn * 64 + (l & 15);
    const int khalf = l >> 4;

    for (int c = 0; c < 4; c++) {
        if (c < 3) {
            stage_all(smem + ((c + 1) & 1) * GSTAGE, m0, n0, (c + 1) * 64, t);
            CP_COMMIT();
            CP_WAIT(1);
        } else {
            CP_WAIT(0);
        }
        __syncthreads();
        const uint32_t sb  = sbase + (c & 1) * GSTAGE;
        const uint32_t sAh = sb, sAl = sb + GT, sBh = sb + 2 * GT, sBl = sb + 3 * GT;
        #pragma unroll
        for (int ks = 0; ks < 4; ks++) {
            const int kb = ks * 2 + khalf;
            uint32_t A[2][4], Bh[4][4], Bl[4][4];
            ldsm4(A[0], swaddr(sAh, rA,      kb));
            ldsm4(A[1], swaddr(sAh, rA + 16, kb));
            #pragma unroll
            for (int nj = 0; nj < 4; nj++) {
                ldsm4(Bh[nj], swaddr(sBh, rB + nj * 16, kb));
                ldsm4(Bl[nj], swaddr(sBl, rB + nj * 16, kb));
            }
            #pragma unroll
            for (int mi = 0; mi < 2; mi++)
                #pragma unroll
                for (int nj = 0; nj < 4; nj++) {
                    mma16816(acc[mi][nj * 2],     A[mi], Bh[nj][0], Bh[nj][2]);
                    mma16816(acc[mi][nj * 2 + 1], A[mi], Bh[nj][1], Bh[nj][3]);
                    mma16816(acc[mi][nj * 2],     A[mi], Bl[nj][0], Bl[nj][2]);
                    mma16816(acc[mi][nj * 2 + 1], A[mi], Bl[nj][1], Bl[nj][3]);
                }
            ldsm4(A[0], swaddr(sAl, rA,      kb));
            ldsm4(A[1], swaddr(sAl, rA + 16, kb));
            #pragma unroll
            for (int mi = 0; mi < 2; mi++)
                #pragma unroll
                for (int nj = 0; nj < 4; nj++) {
                    mma16816(acc[mi][nj * 2],     A[mi], Bh[nj][0], Bh[nj][2]);
                    mma16816(acc[mi][nj * 2 + 1], A[mi], Bh[nj][1], Bh[nj][3]);
                }
        }
        __syncthreads();
    }

    // epilogue: fused self-loop scaling + bias
    #pragma unroll
    for (int mi = 0; mi < 2; mi++) {
        #pragma unroll
        for (int h = 0; h < 2; h++) {
            const int row = m0 + wm * 32 + mi * 16 + (l >> 2) + h * 8;
            if (row >= N_NODES) continue;
            const float dv  = (row < N_USERS) ? g_dinv[row] : 1.0f;
            const float dsq = dv * dv;
            #pragma unroll
            for (int ni = 0; ni < 8; ni++) {
                const int col = n0 + wn * 64 + ni * 8 + 2 * (l & 3);
                const float x = acc[mi][ni][h * 2 + 0];
                const float y = acc[mi][ni][h * 2 + 1];
                const size_t off = (size_t)row * HID + col;
                *(float2*)(g_xw + off) = make_float2(x, y);
                const float2 bb = *(const float2*)(gb + col);
                *(float2*)(out + off) = make_float2(fmaf(x, dsq, bb.x), fmaf(y, dsq, bb.y));
            }
        }
    }
}

// ---------------- K6: scatter messages (vectorized L2 reductions) ---------
__global__ __launch_bounds__(256) void k_scatter(float* __restrict__ out) {
    const int kept = g_cnt[1];
    const long long total = (long long)kept * (HID / 4);
    const long long stride = (long long)gridDim.x * blockDim.x;
    for (long long idx = (long long)blockIdx.x * blockDim.x + threadIdx.x;
         idx < total; idx += stride) {
        const int i = (int)(idx >> 6);
        const int q = (int)(idx & 63);
        const int s = g_ksrc[i];
        const int d = g_kdst[i];
        const float coef = g_dinv[s] * g_dinv[d];
        float4 v = *(const float4*)(g_xw + (size_t)s * HID + q * 4);
        float* p = out + (size_t)d * HID + q * 4;
        asm volatile("red.global.add.v4.f32 [%0], {%1,%2,%3,%4};"
                     :: "l"(p), "f"(v.x * coef), "f"(v.y * coef),
                        "f"(v.z * coef), "f"(v.w * coef)
                     : "memory");
    }
}

// ---------------- host launch ---------------------------------------------
extern "C" void kernel_launch(void* const* d_in, const int* in_sizes, int n_in,
                              void* d_out, int out_size) {
    const float* ue = (const float*)d_in[0];
    const float* ie = (const float*)d_in[1];
    const int*   ei = (const int*)  d_in[2];
    const float* W1 = (const float*)d_in[3];
    const float* b1 = (const float*)d_in[4];
    const float* W2 = (const float*)d_in[5];
    const float* b2 = (const float*)d_in[6];
    const float* gW = (const float*)d_in[7];
    const float* gb = (const float*)d_in[8];
    float* out   = (float*)d_out;
    float* out_w = out + (size_t)N_NODES * HID;

    cudaFuncSetAttribute(k_gemm, cudaFuncAttributeMaxDynamicSharedMemorySize, GSMEM);

    k_reset<<<(N_USERS + 255) / 256, 256>>>();
    k_conv_w<<<(HID * HID + 255) / 256, 256>>>(gW);
    k_conv_x<<<(N_NODES * (HID / 4) + 255) / 256, 256>>>(ue, ie);
    k_attn_pre<<<N_NODES / 8, 256>>>(ue, ie, W1, b1);
    k_edge<<<(N_EDGES + 255) / 256, 256>>>(ei, W2, b2);
    k_denoise<<<(N_EDGES + 255) / 256, 256>>>(ei, out_w);
    k_dinv<<<(N_USERS + 255) / 256, 256>>>();
    dim3 gg((N_NODES + 127) / 128, 2);
    k_gemm<<<gg, 256, GSMEM>>>(gb, out);
    k_scatter<<<1024, 256>>>(out);
}

// round 6
// speedup vs baseline: 1.9517x; 1.4764x over previous
#include <cuda_runtime.h>
#include <cuda_bf16.h>
#include <math.h>
#include <stdint.h>

#define N_USERS 10000
#define N_ITEMS 30000
#define N_NODES 40000
#define HID     256
#define N_EDGES 500000
#define AH      32

// ---------------- scratch (static device allocations only) ----------------
__device__ float g_U1[N_USERS * AH];
__device__ float g_I1[N_ITEMS * AH];
__device__ float g_ew[N_EDGES];
__device__ int   g_ksrc[N_EDGES];
__device__ int   g_kdst[N_EDGES];
__device__ float g_deg[N_USERS];
__device__ float g_dinv[N_USERS];
__device__ float g_xw[(size_t)N_NODES * HID];
__device__ int   g_cnt[2];
__device__ unsigned long long g_maxpack;
// bf16-split operands (K-major)
__device__ __align__(16) __nv_bfloat16 g_Xhi[(size_t)N_NODES * HID];
__device__ __align__(16) __nv_bfloat16 g_Xlo[(size_t)N_NODES * HID];
__device__ __align__(16) __nv_bfloat16 g_Whi[HID * HID];       // gcn W^T: [n][k]
__device__ __align__(16) __nv_bfloat16 g_Wlo[HID * HID];
__device__ __align__(16) __nv_bfloat16 g_A1hi[2 * AH * HID];   // attn W1^T: [half][n][k]
__device__ __align__(16) __nv_bfloat16 g_A1lo[2 * AH * HID];

// ---------------- helpers ---------------------------------------------------
__device__ __forceinline__ uint32_t smem_u32(const void* p) {
    uint32_t a;
    asm("{ .reg .u64 t; cvta.to.shared.u64 t, %1; cvt.u32.u64 %0, t; }" : "=r"(a) : "l"(p));
    return a;
}
__device__ __forceinline__ void ldsm4(uint32_t* f, uint32_t addr) {
    asm volatile("ldmatrix.sync.aligned.m8n8.x4.shared.b16 {%0,%1,%2,%3}, [%4];"
        : "=r"(f[0]), "=r"(f[1]), "=r"(f[2]), "=r"(f[3]) : "r"(addr));
}
__device__ __forceinline__ void mma16816(float* d, const uint32_t* a, uint32_t b0, uint32_t b1) {
    asm volatile("mma.sync.aligned.m16n8k16.row.col.f32.bf16.bf16.f32 "
        "{%0,%1,%2,%3}, {%4,%5,%6,%7}, {%8,%9}, {%0,%1,%2,%3};"
        : "+f"(d[0]), "+f"(d[1]), "+f"(d[2]), "+f"(d[3])
        : "r"(a[0]), "r"(a[1]), "r"(a[2]), "r"(a[3]), "r"(b0), "r"(b1));
}
#define CP_ASYNC16(s, g) asm volatile("cp.async.cg.shared.global [%0], [%1], 16;" :: "r"(s), "l"(g))
#define CP_COMMIT()      asm volatile("cp.async.commit_group;" ::: "memory")
#define CP_WAIT(n)       asm volatile("cp.async.wait_group %0;" :: "n"(n) : "memory")

// swizzled smem offset: row r (128B rows), 16B chunk kb
__device__ __forceinline__ uint32_t swaddr(uint32_t base, int r, int kb) {
    return base + (uint32_t)(r * 128) + (uint32_t)(((kb ^ (r & 7)) << 4));
}

// ---------------- K0: per-launch state reset ------------------------------
__global__ void k_reset() {
    int i = blockIdx.x * blockDim.x + threadIdx.x;
    if (i < N_USERS) g_deg[i] = 1.0f;
    if (i == 0) { g_cnt[0] = 0; g_cnt[1] = 0; g_maxpack = 0ull; }
}

// ---------------- K_conv: fp32 -> bf16 hi/lo splits -----------------------
__global__ __launch_bounds__(256) void k_conv_x(const float* __restrict__ ue,
                                                const float* __restrict__ ie) {
    int i = blockIdx.x * blockDim.x + threadIdx.x;
    if (i >= N_NODES * (HID / 4)) return;
    int row = i >> 6, q = i & 63;
    const float* src = (row < N_USERS) ? (ue + (size_t)row * HID)
                                       : (ie + (size_t)(row - N_USERS) * HID);
    float4 v = ((const float4*)src)[q];
    __nv_bfloat162 h0 = __float22bfloat162_rn(make_float2(v.x, v.y));
    __nv_bfloat162 h1 = __float22bfloat162_rn(make_float2(v.z, v.w));
    float2 f0 = __bfloat1622float2(h0), f1 = __bfloat1622float2(h1);
    __nv_bfloat162 l0 = __float22bfloat162_rn(make_float2(v.x - f0.x, v.y - f0.y));
    __nv_bfloat162 l1 = __float22bfloat162_rn(make_float2(v.z - f1.x, v.w - f1.y));
    ((__nv_bfloat162*)g_Xhi)[i * 2]     = h0;
    ((__nv_bfloat162*)g_Xhi)[i * 2 + 1] = h1;
    ((__nv_bfloat162*)g_Xlo)[i * 2]     = l0;
    ((__nv_bfloat162*)g_Xlo)[i * 2 + 1] = l1;
}

__global__ __launch_bounds__(256) void k_conv_w(const float* __restrict__ W,
                                                const float* __restrict__ W1) {
    int i = blockIdx.x * blockDim.x + threadIdx.x;
    if (i < HID * HID) {                       // gcn W^T
        int n = i >> 8, k = i & 255;
        float v = W[k * HID + n];
        __nv_bfloat16 h = __float2bfloat16(v);
        g_Whi[i] = h;
        g_Wlo[i] = __float2bfloat16(v - __bfloat162float(h));
    }
    int j = i - HID * HID;                     // attn W1^T: [half][n][k]
    if (j >= 0 && j < 2 * AH * HID) {
        int half = j >> 13, rem = j & 8191;
        int n = rem >> 8, k = rem & 255;
        float v = W1[(half * HID + k) * AH + n];
        __nv_bfloat16 h = __float2bfloat16(v);
        g_A1hi[j] = h;
        g_A1lo[j] = __float2bfloat16(v - __bfloat162float(h));
    }
}

// ---------------- K1: attention layer-1 via HMMA bf16x3 -------------------
// CTA: 128 rows x 32 cols, K=256 in 4 chunks of 64.
// smem: B (hi 16KB + lo 16KB, chunk-major 32x128B blocks) + 2 A stages (32KB each).
#define AT_BSZ   16384
#define AT_AT    16384
#define AT_ASTG  (2 * AT_AT)
#define AT_SMEM  (2 * AT_BSZ + 2 * AT_ASTG)
#define N_UBLK   ((N_USERS + 127) / 128)       // 79
#define N_IBLK   ((N_ITEMS + 127) / 128)       // 235

__device__ __forceinline__ void at_stage_a(uint32_t sA, int row0, int ko, int rmax, int t) {
    #pragma unroll
    for (int i = t; i < 1024; i += 256) {
        int r = i >> 3, j = i & 7;
        int gr = row0 + r; if (gr > rmax) gr = rmax;
        size_t go = (size_t)gr * HID + ko + j * 8;
        uint32_t so = swaddr(sA, r, j);
        CP_ASYNC16(so,         g_Xhi + go);
        CP_ASYNC16(so + AT_AT, g_Xlo + go);
    }
}

__global__ __launch_bounds__(256, 1) void k_attn_mma(const float* __restrict__ b1) {
    extern __shared__ char smem[];
    const int t = threadIdx.x, l = t & 31, wrp = t >> 5;
    const int b = blockIdx.x;
    const int half = (b < N_UBLK) ? 0 : 1;
    const int row0 = half ? (N_USERS + (b - N_UBLK) * 128) : b * 128;
    const int rmax = half ? (N_NODES - 1) : (N_USERS - 1);

    const uint32_t sb  = smem_u32(smem);
    const uint32_t sBh = sb, sBl = sb + AT_BSZ, sA = sb + 2 * AT_BSZ;

    // B: [half] 32 n-rows x 256 k, chunk-major: chunk c -> 32 rows x 128B
    {
        const __nv_bfloat16* srcH = g_A1hi + half * (AH * HID);
        const __nv_bfloat16* srcL = g_A1lo + half * (AH * HID);
        #pragma unroll
        for (int i = t; i < 1024; i += 256) {
            int c = i >> 8, n = (i >> 3) & 31, j = i & 7;
            size_t go = (size_t)n * HID + c * 64 + j * 8;
            uint32_t so = swaddr(c * 4096, n, j);
            CP_ASYNC16(sBh + so, srcH + go);
            CP_ASYNC16(sBl + so, srcL + go);
        }
    }
    at_stage_a(sA, row0, 0, rmax, t);
    CP_COMMIT();

    float acc[4][4] = {};
    const int rA = wrp * 16 + (l & 15);        // warp tile: 16 rows x 32 cols
    const int khalf = l >> 4;

    for (int c = 0; c < 4; c++) {
        if (c < 3) {
            at_stage_a(sA + ((c + 1) & 1) * AT_ASTG, row0, (c + 1) * 64, rmax, t);
            CP_COMMIT();
            CP_WAIT(1);
        } else {
            CP_WAIT(0);
        }
        __syncthreads();
        const uint32_t sAc = sA + (c & 1) * AT_ASTG;
        #pragma unroll
        for (int ks = 0; ks < 4; ks++) {
            const int kb = ks * 2 + khalf;
            uint32_t Ah[4], Al[4], Bh[2][4], Bl[2][4];
            ldsm4(Ah, swaddr(sAc, rA, kb));
            ldsm4(Al, swaddr(sAc + AT_AT, rA, kb));
            ldsm4(Bh[0], swaddr(sBh + c * 4096, (l & 15),      kb));
            ldsm4(Bh[1], swaddr(sBh + c * 4096, 16 + (l & 15), kb));
            ldsm4(Bl[0], swaddr(sBl + c * 4096, (l & 15),      kb));
            ldsm4(Bl[1], swaddr(sBl + c * 4096, 16 + (l & 15), kb));
            #pragma unroll
            for (int nj = 0; nj < 4; nj++) {
                const int nb = nj >> 1, p = nj & 1;
                mma16816(acc[nj], Ah, Bh[nb][p], Bh[nb][p + 2]);
                mma16816(acc[nj], Ah, Bl[nb][p], Bl[nb][p + 2]);
                mma16816(acc[nj], Al, Bh[nb][p], Bh[nb][p + 2]);
            }
        }
        __syncthreads();
    }

    // epilogue -> g_U1 / g_I1 (+ b1 for item half)
    #pragma unroll
    for (int h = 0; h < 2; h++) {
        const int r = row0 + wrp * 16 + (l >> 2) + h * 8;
        if (r > rmax) continue;
        #pragma unroll
        for (int nj = 0; nj < 4; nj++) {
            const int col = nj * 8 + 2 * (l & 3);
            float x = acc[nj][h * 2 + 0];
            float y = acc[nj][h * 2 + 1];
            if (half) {
                x += b1[col]; y += b1[col + 1];
                *(float2*)(g_I1 + (size_t)(r - N_USERS) * AH + col) = make_float2(x, y);
            } else {
                *(float2*)(g_U1 + (size_t)r * AH + col) = make_float2(x, y);
            }
        }
    }
}

// ---------------- K2: per-edge MLP tail + sigmoid + stats -----------------
__global__ __launch_bounds__(256) void k_edge(
    const int* __restrict__ ei, const float* __restrict__ W2,
    const float* __restrict__ b2) {
    __shared__ float w2s[32];
    __shared__ float b2s;
    if (threadIdx.x < 32) w2s[threadIdx.x] = W2[threadIdx.x];
    if (threadIdx.x == 0) b2s = b2[0];
    __syncthreads();

    const int e = blockIdx.x * blockDim.x + threadIdx.x;
    bool pass = false;
    unsigned long long pack = 0ull;
    if (e < N_EDGES) {
        const int s = ei[e];
        const int d = ei[N_EDGES + e];
        const float4* up = (const float4*)(g_U1 + (size_t)s * AH);
        const float4* ip = (const float4*)(g_I1 + (size_t)d * AH);
        float logit = b2s;
        #pragma unroll
        for (int q = 0; q < 8; q++) {
            float4 u = up[q], v = ip[q];
            float h;
            h = u.x + v.x; h = h > 0.0f ? h : 0.2f * h; logit = fmaf(h, w2s[q * 4 + 0], logit);
            h = u.y + v.y; h = h > 0.0f ? h : 0.2f * h; logit = fmaf(h, w2s[q * 4 + 1], logit);
            h = u.z + v.z; h = h > 0.0f ? h : 0.2f * h; logit = fmaf(h, w2s[q * 4 + 2], logit);
            h = u.w + v.w; h = h > 0.0f ? h : 0.2f * h; logit = fmaf(h, w2s[q * 4 + 3], logit);
        }
        float w = 1.0f / (1.0f + expf(-logit));
        g_ew[e] = w;
        pass = (w > 0.8f);
        pack = ((unsigned long long)__float_as_uint(w) << 32)
             | (unsigned long long)(~(unsigned)e);
    }
    unsigned m = __ballot_sync(0xffffffffu, pass);
    #pragma unroll
    for (int off = 16; off; off >>= 1) {
        unsigned long long o = __shfl_down_sync(0xffffffffu, pack, off);
        if (o > pack) pack = o;
    }
    if ((threadIdx.x & 31) == 0) {
        if (m) atomicAdd(&g_cnt[0], __popc(m));
        atomicMax(&g_maxpack, pack);
    }
}

// ---------------- K3: denoise + warp-aggregated compaction ----------------
__global__ __launch_bounds__(256) void k_denoise(
    const int* __restrict__ ei, float* __restrict__ out_w) {
    const int e = blockIdx.x * blockDim.x + threadIdx.x;
    bool keep = false;
    float w = 0.0f;
    if (e < N_EDGES) {
        w = g_ew[e];
        if (g_cnt[0] > 0) keep = (w > 0.8f);
        else keep = (e == (int)(~(unsigned)(g_maxpack & 0xffffffffull)));
        out_w[e] = keep ? w : 0.0f;
    }
    unsigned m = __ballot_sync(0xffffffffu, keep);
    if (!m) return;
    const int lane = threadIdx.x & 31;
    const int leader = __ffs(m) - 1;
    int base = 0;
    if (lane == leader) base = atomicAdd(&g_cnt[1], __popc(m));
    base = __shfl_sync(0xffffffffu, base, leader);
    if (keep) {
        const int rank = __popc(m & ((1u << lane) - 1));
        const int s = ei[e];
        const int d = ei[N_EDGES + e];
        g_ksrc[base + rank] = s;
        g_kdst[base + rank] = d;
        atomicAdd(&g_deg[d], 1.0f);
    }
}

// ---------------- K4: dinv = rsqrt(deg) -----------------------------------
__global__ void k_dinv() {
    int i = blockIdx.x * blockDim.x + threadIdx.x;
    if (i < N_USERS) g_dinv[i] = rsqrtf(g_deg[i]);
}

// ---------------- K5: HMMA bf16x3 GEMM, fused self-loop + bias ------------
#define GT      16384
#define GSTAGE  (4 * GT)
#define GSMEM   (2 * GSTAGE)

__device__ __forceinline__ void stage_all(char* dst, int m0, int n0, int ko, int t) {
    uint32_t sb = smem_u32(dst);
    #pragma unroll
    for (int i = t; i < 1024; i += 256) {
        int r = i >> 3, kb = i & 7;
        int gr = m0 + r; if (gr > N_NODES - 1) gr = N_NODES - 1;
        size_t go = (size_t)gr * HID + ko + kb * 8;
        uint32_t so = sb + (uint32_t)(r * 128) + (uint32_t)(((kb ^ (r & 7)) << 4));
        CP_ASYNC16(so,          g_Xhi + go);
        CP_ASYNC16(so + GT,     g_Xlo + go);
        int br = n0 + r;
        size_t bo = (size_t)br * HID + ko + kb * 8;
        CP_ASYNC16(so + 2 * GT, g_Whi + bo);
        CP_ASYNC16(so + 3 * GT, g_Wlo + bo);
    }
}

__global__ __launch_bounds__(256, 1) void k_gemm(const float* __restrict__ gb,
                                                 float* __restrict__ out) {
    extern __shared__ char smem[];
    const int t = threadIdx.x;
    const int l = t & 31, wrp = t >> 5;
    const int wm = wrp & 3, wn = wrp >> 2;
    const int m0 = blockIdx.x * 128, n0 = blockIdx.y * 128;
    const uint32_t sbase = smem_u32(smem);

    stage_all(smem, m0, n0, 0, t);
    CP_COMMIT();

    float acc[2][8][4] = {};
    const int rA = wm * 32 + (l & 15);
    const int rB = wn * 64 + (l & 15);
    const int khalf = l >> 4;

    for (int c = 0; c < 4; c++) {
        if (c < 3) {
            stage_all(smem + ((c + 1) & 1) * GSTAGE, m0, n0, (c + 1) * 64, t);
            CP_COMMIT();
            CP_WAIT(1);
        } else {
            CP_WAIT(0);
        }
        __syncthreads();
        const uint32_t sb  = sbase + (c & 1) * GSTAGE;
        const uint32_t sAh = sb, sAl = sb + GT, sBh = sb + 2 * GT, sBl = sb + 3 * GT;
        #pragma unroll
        for (int ks = 0; ks < 4; ks++) {
            const int kb = ks * 2 + khalf;
            uint32_t A[2][4], Bh[4][4], Bl[4][4];
            ldsm4(A[0], swaddr(sAh, rA,      kb));
            ldsm4(A[1], swaddr(sAh, rA + 16, kb));
            #pragma unroll
            for (int nj = 0; nj < 4; nj++) {
                ldsm4(Bh[nj], swaddr(sBh, rB + nj * 16, kb));
                ldsm4(Bl[nj], swaddr(sBl, rB + nj * 16, kb));
            }
            #pragma unroll
            for (int mi = 0; mi < 2; mi++)
                #pragma unroll
                for (int nj = 0; nj < 4; nj++) {
                    mma16816(acc[mi][nj * 2],     A[mi], Bh[nj][0], Bh[nj][2]);
                    mma16816(acc[mi][nj * 2 + 1], A[mi], Bh[nj][1], Bh[nj][3]);
                    mma16816(acc[mi][nj * 2],     A[mi], Bl[nj][0], Bl[nj][2]);
                    mma16816(acc[mi][nj * 2 + 1], A[mi], Bl[nj][1], Bl[nj][3]);
                }
            ldsm4(A[0], swaddr(sAl, rA,      kb));
            ldsm4(A[1], swaddr(sAl, rA + 16, kb));
            #pragma unroll
            for (int mi = 0; mi < 2; mi++)
                #pragma unroll
                for (int nj = 0; nj < 4; nj++) {
                    mma16816(acc[mi][nj * 2],     A[mi], Bh[nj][0], Bh[nj][2]);
                    mma16816(acc[mi][nj * 2 + 1], A[mi], Bh[nj][1], Bh[nj][3]);
                }
        }
        __syncthreads();
    }

    #pragma unroll
    for (int mi = 0; mi < 2; mi++) {
        #pragma unroll
        for (int h = 0; h < 2; h++) {
            const int row = m0 + wm * 32 + mi * 16 + (l >> 2) + h * 8;
            if (row >= N_NODES) continue;
            const float dv  = (row < N_USERS) ? g_dinv[row] : 1.0f;
            const float dsq = dv * dv;
            #pragma unroll
            for (int ni = 0; ni < 8; ni++) {
                const int col = n0 + wn * 64 + ni * 8 + 2 * (l & 3);
                const float x = acc[mi][ni][h * 2 + 0];
                const float y = acc[mi][ni][h * 2 + 1];
                const size_t off = (size_t)row * HID + col;
                *(float2*)(g_xw + off) = make_float2(x, y);
                const float2 bb = *(const float2*)(gb + col);
                *(float2*)(out + off) = make_float2(fmaf(x, dsq, bb.x), fmaf(y, dsq, bb.y));
            }
        }
    }
}

// ---------------- K6: scatter messages (vectorized L2 reductions) ---------
__global__ __launch_bounds__(256) void k_scatter(float* __restrict__ out) {
    const int kept = g_cnt[1];
    const long long total = (long long)kept * (HID / 4);
    const long long stride = (long long)gridDim.x * blockDim.x;
    for (long long idx = (long long)blockIdx.x * blockDim.x + threadIdx.x;
         idx < total; idx += stride) {
        const int i = (int)(idx >> 6);
        const int q = (int)(idx & 63);
        const int s = g_ksrc[i];
        const int d = g_kdst[i];
        const float coef = g_dinv[s] * g_dinv[d];
        float4 v = *(const float4*)(g_xw + (size_t)s * HID + q * 4);
        float* p = out + (size_t)d * HID + q * 4;
        asm volatile("red.global.add.v4.f32 [%0], {%1,%2,%3,%4};"
                     :: "l"(p), "f"(v.x * coef), "f"(v.y * coef),
                        "f"(v.z * coef), "f"(v.w * coef)
                     : "memory");
    }
}

// ---------------- host launch ---------------------------------------------
extern "C" void kernel_launch(void* const* d_in, const int* in_sizes, int n_in,
                              void* d_out, int out_size) {
    const float* ue = (const float*)d_in[0];
    const float* ie = (const float*)d_in[1];
    const int*   ei = (const int*)  d_in[2];
    const float* W1 = (const float*)d_in[3];
    const float* b1 = (const float*)d_in[4];
    const float* W2 = (const float*)d_in[5];
    const float* b2 = (const float*)d_in[6];
    const float* gW = (const float*)d_in[7];
    const float* gb = (const float*)d_in[8];
    float* out   = (float*)d_out;
    float* out_w = out + (size_t)N_NODES * HID;

    cudaFuncSetAttribute(k_gemm,     cudaFuncAttributeMaxDynamicSharedMemorySize, GSMEM);
    cudaFuncSetAttribute(k_attn_mma, cudaFuncAttributeMaxDynamicSharedMemorySize, AT_SMEM);

    k_reset<<<(N_USERS + 255) / 256, 256>>>();
    k_conv_w<<<(HID * HID + 2 * AH * HID + 255) / 256, 256>>>(gW, W1);
    k_conv_x<<<(N_NODES * (HID / 4) + 255) / 256, 256>>>(ue, ie);
    k_attn_mma<<<N_UBLK + N_IBLK, 256, AT_SMEM>>>(b1);
    k_edge<<<(N_EDGES + 255) / 256, 256>>>(ei, W2, b2);
    k_denoise<<<(N_EDGES + 255) / 256, 256>>>(ei, out_w);
    k_dinv<<<(N_USERS + 255) / 256, 256>>>();
    dim3 gg((N_NODES + 127) / 128, 2);
    k_gemm<<<gg, 256, GSMEM>>>(gb, out);
    k_scatter<<<1024, 256>>>(out);
}

// round 8
// speedup vs baseline: 2.1690x; 1.1113x over previous
#include <cuda_runtime.h>
#include <cuda_bf16.h>
#include <math.h>
#include <stdint.h>

#define N_USERS 10000
#define N_ITEMS 30000
#define N_NODES 40000
#define HID     256
#define N_EDGES 500000
#define AH      32

// ---------------- scratch (static device allocations only) ----------------
__device__ float g_U1[N_USERS * AH];
__device__ float g_I1[N_ITEMS * AH];
__device__ int   g_ksrc[N_EDGES];
__device__ int   g_kdst[N_EDGES];
__device__ float g_deg[N_USERS];
__device__ float g_dinv[N_USERS];
__device__ float g_xw[(size_t)N_USERS * HID];        // only user rows needed by scatter
__device__ int   g_cnt[1];                           // kept-edge count
__device__ unsigned long long g_maxpack;             // (w_bits<<32) | ~e
// bf16-split operands (K-major)
__device__ __align__(16) __nv_bfloat16 g_Xhi[(size_t)N_NODES * HID];
__device__ __align__(16) __nv_bfloat16 g_Xlo[(size_t)N_NODES * HID];
__device__ __align__(16) __nv_bfloat16 g_Whi[HID * HID];       // gcn W^T: [n][k]
__device__ __align__(16) __nv_bfloat16 g_Wlo[HID * HID];
__device__ __align__(16) __nv_bfloat16 g_A1hi[2 * AH * HID];   // attn W1^T: [half][n][k]
__device__ __align__(16) __nv_bfloat16 g_A1lo[2 * AH * HID];

// ---------------- helpers ---------------------------------------------------
__device__ __forceinline__ uint32_t smem_u32(const void* p) {
    uint32_t a;
    asm("{ .reg .u64 t; cvta.to.shared.u64 t, %1; cvt.u32.u64 %0, t; }" : "=r"(a) : "l"(p));
    return a;
}
__device__ __forceinline__ void ldsm4(uint32_t* f, uint32_t addr) {
    asm volatile("ldmatrix.sync.aligned.m8n8.x4.shared.b16 {%0,%1,%2,%3}, [%4];"
        : "=r"(f[0]), "=r"(f[1]), "=r"(f[2]), "=r"(f[3]) : "r"(addr));
}
__device__ __forceinline__ void mma16816(float* d, const uint32_t* a, uint32_t b0, uint32_t b1) {
    asm volatile("mma.sync.aligned.m16n8k16.row.col.f32.bf16.bf16.f32 "
        "{%0,%1,%2,%3}, {%4,%5,%6,%7}, {%8,%9}, {%0,%1,%2,%3};"
        : "+f"(d[0]), "+f"(d[1]), "+f"(d[2]), "+f"(d[3])
        : "r"(a[0]), "r"(a[1]), "r"(a[2]), "r"(a[3]), "r"(b0), "r"(b1));
}
#define CP_ASYNC16(s, g) asm volatile("cp.async.cg.shared.global [%0], [%1], 16;" :: "r"(s), "l"(g))
#define CP_COMMIT()      asm volatile("cp.async.commit_group;" ::: "memory")
#define CP_WAIT(n)       asm volatile("cp.async.wait_group %0;" :: "n"(n) : "memory")

__device__ __forceinline__ uint32_t swaddr(uint32_t base, int r, int kb) {
    return base + (uint32_t)(r * 128) + (uint32_t)(((kb ^ (r & 7)) << 4));
}

// ---------------- K_prep: reset + weight conv + X hi/lo split (fused) -----
#define CXN (N_NODES * (HID / 4))
__global__ __launch_bounds__(256) void k_prep(
    const float* __restrict__ ue, const float* __restrict__ ie,
    const float* __restrict__ W,  const float* __restrict__ W1) {
    const int i = blockIdx.x * blockDim.x + threadIdx.x;
    if (i < CXN) {                              // X fp32 -> bf16 hi/lo, one float4
        int row = i >> 6, q = i & 63;
        const float* src = (row < N_USERS) ? (ue + (size_t)row * HID)
                                           : (ie + (size_t)(row - N_USERS) * HID);
        float4 v = ((const float4*)src)[q];
        __nv_bfloat162 h0 = __float22bfloat162_rn(make_float2(v.x, v.y));
        __nv_bfloat162 h1 = __float22bfloat162_rn(make_float2(v.z, v.w));
        float2 f0 = __bfloat1622float2(h0), f1 = __bfloat1622float2(h1);
        __nv_bfloat162 l0 = __float22bfloat162_rn(make_float2(v.x - f0.x, v.y - f0.y));
        __nv_bfloat162 l1 = __float22bfloat162_rn(make_float2(v.z - f1.x, v.w - f1.y));
        ((__nv_bfloat162*)g_Xhi)[i * 2]     = h0;
        ((__nv_bfloat162*)g_Xhi)[i * 2 + 1] = h1;
        ((__nv_bfloat162*)g_Xlo)[i * 2]     = l0;
        ((__nv_bfloat162*)g_Xlo)[i * 2 + 1] = l1;
    }
    if (i < HID * HID) {                        // gcn W^T split
        int n = i >> 8, k = i & 255;
        float v = W[k * HID + n];
        __nv_bfloat16 h = __float2bfloat16(v);
        g_Whi[i] = h;
        g_Wlo[i] = __float2bfloat16(v - __bfloat162float(h));
    }
    if (i < 2 * AH * HID) {                     // attn W1^T split: [half][n][k]
        int half = i >> 13, rem = i & 8191;
        int n = rem >> 8, k = rem & 255;
        float v = W1[(half * HID + k) * AH + n];
        __nv_bfloat16 h = __float2bfloat16(v);
        g_A1hi[i] = h;
        g_A1lo[i] = __float2bfloat16(v - __bfloat162float(h));
    }
    if (i < N_USERS) g_deg[i] = 1.0f;
    if (i == 0) { g_cnt[0] = 0; g_maxpack = 0ull; }
}

// ---------------- K1: attention layer-1, 256-row CTAs ---------------------
// CTA: 256 rows x 32 cols, K=256 in 4 chunks of 64.
// smem: B (hi+lo 32KB, chunk-major) + 2 A stages of (hi+lo 64KB).
#define AT_BSZ   16384
#define AT_AT    32768
#define AT_ASTG  (2 * AT_AT)
#define AT_SMEM  (2 * AT_BSZ + 2 * AT_ASTG)     // 160KB
#define N_UBLK   ((N_USERS + 255) / 256)        // 40
#define N_IBLK   ((N_ITEMS + 255) / 256)        // 118

__device__ __forceinline__ void at_stage_a(uint32_t sA, int row0, int ko, int rmax, int t) {
    #pragma unroll
    for (int i = t; i < 2048; i += 256) {
        int r = i >> 3, j = i & 7;
        int gr = row0 + r; if (gr > rmax) gr = rmax;
        size_t go = (size_t)gr * HID + ko + j * 8;
        uint32_t so = swaddr(sA, r, j);
        CP_ASYNC16(so,         g_Xhi + go);
        CP_ASYNC16(so + AT_AT, g_Xlo + go);
    }
}

__global__ __launch_bounds__(256, 1) void k_attn_mma(const float* __restrict__ b1) {
    extern __shared__ char smem[];
    const int t = threadIdx.x, l = t & 31, wrp = t >> 5;
    const int b = blockIdx.x;
    const int half = (b < N_UBLK) ? 0 : 1;
    const int row0 = half ? (N_USERS + (b - N_UBLK) * 256) : b * 256;
    const int rmax = half ? (N_NODES - 1) : (N_USERS - 1);

    const uint32_t sb  = smem_u32(smem);
    const uint32_t sBh = sb, sBl = sb + AT_BSZ, sA = sb + 2 * AT_BSZ;

    {   // B: 32 n-rows x 256 k, chunk-major (chunk c -> 32 rows x 128B)
        const __nv_bfloat16* srcH = g_A1hi + half * (AH * HID);
        const __nv_bfloat16* srcL = g_A1lo + half * (AH * HID);
        #pragma unroll
        for (int i = t; i < 1024; i += 256) {
            int c = i >> 8, n = (i >> 3) & 31, j = i & 7;
            size_t go = (size_t)n * HID + c * 64 + j * 8;
            uint32_t so = swaddr(c * 4096, n, j);
            CP_ASYNC16(sBh + so, srcH + go);
            CP_ASYNC16(sBl + so, srcL + go);
        }
    }
    at_stage_a(sA, row0, 0, rmax, t);
    CP_COMMIT();

    float acc[2][4][4] = {};
    const int rA = wrp * 32 + (l & 15);         // warp tile: 32 rows x 32 cols
    const int khalf = l >> 4;

    for (int c = 0; c < 4; c++) {
        if (c < 3) {
            at_stage_a(sA + ((c + 1) & 1) * AT_ASTG, row0, (c + 1) * 64, rmax, t);
            CP_COMMIT();
            CP_WAIT(1);
        } else {
            CP_WAIT(0);
        }
        __syncthreads();
        const uint32_t sAc = sA + (c & 1) * AT_ASTG;
        #pragma unroll
        for (int ks = 0; ks < 4; ks++) {
            const int kb = ks * 2 + khalf;
            uint32_t Ah[2][4], Al[2][4], Bh[2][4], Bl[2][4];
            ldsm4(Ah[0], swaddr(sAc, rA,      kb));
            ldsm4(Ah[1], swaddr(sAc, rA + 16, kb));
            ldsm4(Al[0], swaddr(sAc + AT_AT, rA,      kb));
            ldsm4(Al[1], swaddr(sAc + AT_AT, rA + 16, kb));
            ldsm4(Bh[0], swaddr(sBh + c * 4096, (l & 15),      kb));
            ldsm4(Bh[1], swaddr(sBh + c * 4096, 16 + (l & 15), kb));
            ldsm4(Bl[0], swaddr(sBl + c * 4096, (l & 15),      kb));
            ldsm4(Bl[1], swaddr(sBl + c * 4096, 16 + (l & 15), kb));
            #pragma unroll
            for (int mi = 0; mi < 2; mi++)
                #pragma unroll
                for (int nj = 0; nj < 4; nj++) {
                    const int nb = nj >> 1, p = nj & 1;
                    mma16816(acc[mi][nj], Ah[mi], Bh[nb][p], Bh[nb][p + 2]);
                    mma16816(acc[mi][nj], Ah[mi], Bl[nb][p], Bl[nb][p + 2]);
                    mma16816(acc[mi][nj], Al[mi], Bh[nb][p], Bh[nb][p + 2]);
                }
        }
        __syncthreads();
    }

    #pragma unroll
    for (int mi = 0; mi < 2; mi++) {
        #pragma unroll
        for (int h = 0; h < 2; h++) {
            const int r = row0 + wrp * 32 + mi * 16 + (l >> 2) + h * 8;
            if (r > rmax) continue;
            #pragma unroll
            for (int nj = 0; nj < 4; nj++) {
                const int col = nj * 8 + 2 * (l & 3);
                float x = acc[mi][nj][h * 2 + 0];
                float y = acc[mi][nj][h * 2 + 1];
                if (half) {
                    x += b1[col]; y += b1[col + 1];
                    *(float2*)(g_I1 + (size_t)(r - N_USERS) * AH + col) = make_float2(x, y);
                } else {
                    *(float2*)(g_U1 + (size_t)r * AH + col) = make_float2(x, y);
                }
            }
        }
    }
}

// ---------------- K2: edge MLP tail + sigmoid + denoise + compact (fused) -
__global__ __launch_bounds__(256) void k_edge(
    const int* __restrict__ ei, const float* __restrict__ W2,
    const float* __restrict__ b2, float* __restrict__ out_w) {
    __shared__ float w2s[32];
    __shared__ float b2s;
    if (threadIdx.x < 32) w2s[threadIdx.x] = W2[threadIdx.x];
    if (threadIdx.x == 0) b2s = b2[0];
    __syncthreads();

    const int e = blockIdx.x * blockDim.x + threadIdx.x;
    bool pass = false;
    int s = 0, d = 0;
    unsigned long long pack = 0ull;
    if (e < N_EDGES) {
        s = ei[e];
        d = ei[N_EDGES + e];
        const float4* up = (const float4*)(g_U1 + (size_t)s * AH);
        const float4* ip = (const float4*)(g_I1 + (size_t)d * AH);
        float logit = b2s;
        #pragma unroll
        for (int q = 0; q < 8; q++) {
            float4 u = up[q], v = ip[q];
            float h;
            h = u.x + v.x; h = h > 0.0f ? h : 0.2f * h; logit = fmaf(h, w2s[q * 4 + 0], logit);
            h = u.y + v.y; h = h > 0.0f ? h : 0.2f * h; logit = fmaf(h, w2s[q * 4 + 1], logit);
            h = u.z + v.z; h = h > 0.0f ? h : 0.2f * h; logit = fmaf(h, w2s[q * 4 + 2], logit);
            h = u.w + v.w; h = h > 0.0f ? h : 0.2f * h; logit = fmaf(h, w2s[q * 4 + 3], logit);
        }
        float w = 1.0f / (1.0f + expf(-logit));
        pass = (w > 0.8f);
        out_w[e] = pass ? w : 0.0f;
        pack = ((unsigned long long)__float_as_uint(w) << 32)
             | (unsigned long long)(~(unsigned)e);
    }
    // argmax reduce (for fallback)
    unsigned long long pk = pack;
    #pragma unroll
    for (int off = 16; off; off >>= 1) {
        unsigned long long o = __shfl_down_sync(0xffffffffu, pk, off);
        if (o > pk) pk = o;
    }
    const int lane = threadIdx.x & 31;
    if (lane == 0) atomicMax(&g_maxpack, pk);
    // warp-aggregated compaction
    unsigned m = __ballot_sync(0xffffffffu, pass);
    if (!m) return;
    const int leader = __ffs(m) - 1;
    int base = 0;
    if (lane == leader) base = atomicAdd(&g_cnt[0], __popc(m));
    base = __shfl_sync(0xffffffffu, base, leader);
    if (pass) {
        const int rank = __popc(m & ((1u << lane) - 1));
        g_ksrc[base + rank] = s;
        g_kdst[base + rank] = d;
        atomicAdd(&g_deg[d], 1.0f);
    }
}

// ---------------- K3: fallback (only if no edge passed) -------------------
__global__ void k_fallback(const int* __restrict__ ei, float* __restrict__ out_w) {
    if (threadIdx.x == 0 && g_cnt[0] == 0) {
        const unsigned long long p = g_maxpack;
        const int e = (int)(~(unsigned)(p & 0xffffffffull));
        out_w[e] = __uint_as_float((unsigned)(p >> 32));
        const int s = ei[e];
        const int d = ei[N_EDGES + e];
        g_ksrc[0] = s;
        g_kdst[0] = d;
        g_cnt[0] = 1;
        g_deg[d] += 1.0f;
    }
}

// ---------------- K4: dinv = rsqrt(deg) -----------------------------------
__global__ void k_dinv() {
    int i = blockIdx.x * blockDim.x + threadIdx.x;
    if (i < N_USERS) g_dinv[i] = rsqrtf(g_deg[i]);
}

// ---------------- K5: HMMA bf16x3 GEMM, fused self-loop + bias ------------
#define GT      16384
#define GSTAGE  (4 * GT)
#define GSMEM   (2 * GSTAGE)

__device__ __forceinline__ void stage_all(char* dst, int m0, int n0, int ko, int t) {
    uint32_t sb = smem_u32(dst);
    #pragma unroll
    for (int i = t; i < 1024; i += 256) {
        int r = i >> 3, kb = i & 7;
        int gr = m0 + r; if (gr > N_NODES - 1) gr = N_NODES - 1;
        size_t go = (size_t)gr * HID + ko + kb * 8;
        uint32_t so = sb + (uint32_t)(r * 128) + (uint32_t)(((kb ^ (r & 7)) << 4));
        CP_ASYNC16(so,          g_Xhi + go);
        CP_ASYNC16(so + GT,     g_Xlo + go);
        int br = n0 + r;
        size_t bo = (size_t)br * HID + ko + kb * 8;
        CP_ASYNC16(so + 2 * GT, g_Whi + bo);
        CP_ASYNC16(so + 3 * GT, g_Wlo + bo);
    }
}

__global__ __launch_bounds__(256, 1) void k_gemm(const float* __restrict__ gb,
                                                 float* __restrict__ out) {
    extern __shared__ char smem[];
    const int t = threadIdx.x;
    const int l = t & 31, wrp = t >> 5;
    const int wm = wrp & 3, wn = wrp >> 2;
    const int m0 = blockIdx.x * 128, n0 = blockIdx.y * 128;
    const uint32_t sbase = smem_u32(smem);

    stage_all(smem, m0, n0, 0, t);
    CP_COMMIT();

    float acc[2][8][4] = {};
    const int rA = wm * 32 + (l & 15);
    const int rB = wn * 64 + (l & 15);
    const int khalf = l >> 4;

    for (int c = 0; c < 4; c++) {
        if (c < 3) {
            stage_all(smem + ((c + 1) & 1) * GSTAGE, m0, n0, (c + 1) * 64, t);
            CP_COMMIT();
            CP_WAIT(1);
        } else {
            CP_WAIT(0);
        }
        __syncthreads();
        const uint32_t sb  = sbase + (c & 1) * GSTAGE;
        const uint32_t sAh = sb, sAl = sb + GT, sBh = sb + 2 * GT, sBl = sb + 3 * GT;
        #pragma unroll
        for (int ks = 0; ks < 4; ks++) {
            const int kb = ks * 2 + khalf;
            uint32_t A[2][4], Bh[4][4], Bl[4][4];
            ldsm4(A[0], swaddr(sAh, rA,      kb));
            ldsm4(A[1], swaddr(sAh, rA + 16, kb));
            #pragma unroll
            for (int nj = 0; nj < 4; nj++) {
                ldsm4(Bh[nj], swaddr(sBh, rB + nj * 16, kb));
                ldsm4(Bl[nj], swaddr(sBl, rB + nj * 16, kb));
            }
            #pragma unroll
            for (int mi = 0; mi < 2; mi++)
                #pragma unroll
                for (int nj = 0; nj < 4; nj++) {
                    mma16816(acc[mi][nj * 2],     A[mi], Bh[nj][0], Bh[nj][2]);
                    mma16816(acc[mi][nj * 2 + 1], A[mi], Bh[nj][1], Bh[nj][3]);
                    mma16816(acc[mi][nj * 2],     A[mi], Bl[nj][0], Bl[nj][2]);
                    mma16816(acc[mi][nj * 2 + 1], A[mi], Bl[nj][1], Bl[nj][3]);
                }
            ldsm4(A[0], swaddr(sAl, rA,      kb));
            ldsm4(A[1], swaddr(sAl, rA + 16, kb));
            #pragma unroll
            for (int mi = 0; mi < 2; mi++)
                #pragma unroll
                for (int nj = 0; nj < 4; nj++) {
                    mma16816(acc[mi][nj * 2],     A[mi], Bh[nj][0], Bh[nj][2]);
                    mma16816(acc[mi][nj * 2 + 1], A[mi], Bh[nj][1], Bh[nj][3]);
                }
        }
        __syncthreads();
    }

    #pragma unroll
    for (int mi = 0; mi < 2; mi++) {
        #pragma unroll
        for (int h = 0; h < 2; h++) {
            const int row = m0 + wm * 32 + mi * 16 + (l >> 2) + h * 8;
            if (row >= N_NODES) continue;
            const bool isU = (row < N_USERS);
            const float dv  = isU ? g_dinv[row] : 1.0f;
            const float dsq = dv * dv;
            #pragma unroll
            for (int ni = 0; ni < 8; ni++) {
                const int col = n0 + wn * 64 + ni * 8 + 2 * (l & 3);
                const float x = acc[mi][ni][h * 2 + 0];
                const float y = acc[mi][ni][h * 2 + 1];
                const size_t off = (size_t)row * HID + col;
                if (isU) *(float2*)(g_xw + off) = make_float2(x, y);   // scatter reads users only
                const float2 bb = *(const float2*)(gb + col);
                *(float2*)(out + off) = make_float2(fmaf(x, dsq, bb.x), fmaf(y, dsq, bb.y));
            }
        }
    }
}

// ---------------- K6: scatter messages (vectorized L2 reductions) ---------
__global__ __launch_bounds__(256) void k_scatter(float* __restrict__ out) {
    const int kept = g_cnt[0];
    const long long total = (long long)kept * (HID / 4);
    const long long stride = (long long)gridDim.x * blockDim.x;
    for (long long idx = (long long)blockIdx.x * blockDim.x + threadIdx.x;
         idx < total; idx += stride) {
        const int i = (int)(idx >> 6);
        const int q = (int)(idx & 63);
        const int s = g_ksrc[i];
        const int d = g_kdst[i];
        const float coef = g_dinv[s] * g_dinv[d];
        float4 v = *(const float4*)(g_xw + (size_t)s * HID + q * 4);
        float* p = out + (size_t)d * HID + q * 4;
        asm volatile("red.global.add.v4.f32 [%0], {%1,%2,%3,%4};"
                     :: "l"(p), "f"(v.x * coef), "f"(v.y * coef),
                        "f"(v.z * coef), "f"(v.w * coef)
                     : "memory");
    }
}

// ---------------- host launch ---------------------------------------------
extern "C" void kernel_launch(void* const* d_in, const int* in_sizes, int n_in,
                              void* d_out, int out_size) {
    const float* ue = (const float*)d_in[0];
    const float* ie = (const float*)d_in[1];
    const int*   ei = (const int*)  d_in[2];
    const float* W1 = (const float*)d_in[3];
    const float* b1 = (const float*)d_in[4];
    const float* W2 = (const float*)d_in[5];
    const float* b2 = (const float*)d_in[6];
    const float* gW = (const float*)d_in[7];
    const float* gb = (const float*)d_in[8];
    float* out   = (float*)d_out;
    float* out_w = out + (size_t)N_NODES * HID;

    cudaFuncSetAttribute(k_gemm,     cudaFuncAttributeMaxDynamicSharedMemorySize, GSMEM);
    cudaFuncSetAttribute(k_attn_mma, cudaFuncAttributeMaxDynamicSharedMemorySize, AT_SMEM);

    k_prep<<<(CXN + 255) / 256, 256>>>(ue, ie, gW, W1);
    k_attn_mma<<<N_UBLK + N_IBLK, 256, AT_SMEM>>>(b1);
    k_edge<<<(N_EDGES + 255) / 256, 256>>>(ei, W2, b2, out_w);
    k_fallback<<<1, 32>>>(ei, out_w);
    k_dinv<<<(N_USERS + 255) / 256, 256>>>();
    dim3 gg((N_NODES + 127) / 128, 2);
    k_gemm<<<gg, 256, GSMEM>>>(gb, out);
    k_scatter<<<1024, 256>>>(out);
}